// round 1
// baseline (speedup 1.0000x reference)
#include <cuda_runtime.h>
#include <math.h>

// Problem constants
#define N0c 100000
#define N1c 40000
#define N2c 10000
#define E1c 640000
#define E2c 160000
#define Dc  256      // D_IN == D_HID
#define DOUTc 128

// ---------------- scratch (device globals; no runtime allocation) ------------
__device__ float g_aggr1[(size_t)N1c * Dc];   // 40.96 MB
__device__ float g_h[(size_t)N1c * Dc];       // 40.96 MB
__device__ float g_aggr2[(size_t)N2c * Dc];   // 10.24 MB
__device__ int   g_cnt1[N1c];
__device__ int   g_cnt2[N2c];
__device__ float g_inv1[N1c];
__device__ float g_inv2[N2c];

// ---------------- kernels ----------------------------------------------------

__global__ void count_kernel(const int* __restrict__ dst, int* __restrict__ cnt, int E) {
    int i = blockIdx.x * blockDim.x + threadIdx.x;
    if (i < E) atomicAdd(&cnt[dst[i]], 1);
}

__global__ void inv_kernel(const int* __restrict__ cnt, float* __restrict__ inv, int n) {
    int i = blockIdx.x * blockDim.x + threadIdx.x;
    if (i < n) inv[i] = 1.0f / (float)max(cnt[i], 1);
}

// One warp per edge: gather a 256-float row, vectorized float4 atomic add into dest row.
__global__ void scatter_kernel(const float* __restrict__ X, const int* __restrict__ src,
                               const int* __restrict__ dst, float* __restrict__ out, int E) {
    int gw   = (blockIdx.x * blockDim.x + threadIdx.x) >> 5;
    int lane = threadIdx.x & 31;
    if (gw >= E) return;
    int s = src[gw];
    int d = dst[gw];
    const float4* xr = (const float4*)(X + (size_t)s * Dc);
    float4*       o  = (float4*)(out + (size_t)d * Dc);
    float4 v0 = __ldg(&xr[lane]);
    float4 v1 = __ldg(&xr[lane + 32]);
    atomicAdd(&o[lane], v0);        // sm_90+ vectorized 128-bit reduction
    atomicAdd(&o[lane + 32], v1);
}

// Fused GEMM: C = act( [A0*sc0 | A1] @ [W0 ; W1] + bias ), K = 512 (256 + 256)
// A0, A1: M x 256 row-major. W0, W1: 256 x N row-major. ACT: 0 = relu, 1 = sigmoid.
// Tiles: BM=128, BN=64, BK=16; 256 threads; 8x4 micro-tile per thread.
template <int ACT>
__global__ void __launch_bounds__(256)
gemm_fused(const float* __restrict__ A0, const float* __restrict__ sc0,
           const float* __restrict__ A1,
           const float* __restrict__ W0, const float* __restrict__ W1,
           const float* __restrict__ bias,
           float* __restrict__ C, int M, int N)
{
    const int BM = 128, BN = 64, BK = 16;
    __shared__ float As[BK][BM];   // stored k-major for FMA loop
    __shared__ float Bs[BK][BN];

    const int tid  = threadIdx.x;
    const int row0 = blockIdx.x * BM;
    const int col0 = blockIdx.y * BN;

    const int tx = tid & 15;   // 0..15 -> n
    const int ty = tid >> 4;   // 0..15 -> m

    float acc[8][4];
    #pragma unroll
    for (int i = 0; i < 8; i++)
        #pragma unroll
        for (int j = 0; j < 4; j++) acc[i][j] = 0.0f;

    // A-load mapping: a_k4 = float4 slot in k, a_m = row within tile (2 passes of 64)
    const int a_k4 = tid & 3;
    const int a_m  = tid >> 2;
    // B-load mapping: one float4 per thread
    const int b_k = tid >> 4;
    const int b_n = (tid & 15) * 4;

    for (int k0 = 0; k0 < 512; k0 += BK) {
        const bool   first  = (k0 < 256);
        const float* Asrc   = first ? A0 : A1;
        const float* Wsrc   = first ? W0 : W1;
        const int    kk0    = first ? k0 : (k0 - 256);

        #pragma unroll
        for (int p = 0; p < 2; p++) {
            int m    = a_m + p * 64;
            int grow = row0 + m;
            float4 v = make_float4(0.f, 0.f, 0.f, 0.f);
            if (grow < M) {
                v = *(const float4*)(Asrc + (size_t)grow * 256 + kk0 + a_k4 * 4);
                if (first) {
                    float s = sc0[grow];
                    v.x *= s; v.y *= s; v.z *= s; v.w *= s;
                }
            }
            As[a_k4 * 4 + 0][m] = v.x;
            As[a_k4 * 4 + 1][m] = v.y;
            As[a_k4 * 4 + 2][m] = v.z;
            As[a_k4 * 4 + 3][m] = v.w;
        }
        {
            float4 w = *(const float4*)(Wsrc + (size_t)(kk0 + b_k) * N + col0 + b_n);
            *(float4*)&Bs[b_k][b_n] = w;
        }
        __syncthreads();

        #pragma unroll
        for (int kk = 0; kk < BK; kk++) {
            float4 a0 = *(const float4*)&As[kk][ty * 8];
            float4 a1 = *(const float4*)&As[kk][ty * 8 + 4];
            float4 b  = *(const float4*)&Bs[kk][tx * 4];
            float a[8] = {a0.x, a0.y, a0.z, a0.w, a1.x, a1.y, a1.z, a1.w};
            float bb[4] = {b.x, b.y, b.z, b.w};
            #pragma unroll
            for (int i = 0; i < 8; i++)
                #pragma unroll
                for (int j = 0; j < 4; j++)
                    acc[i][j] = fmaf(a[i], bb[j], acc[i][j]);
        }
        __syncthreads();
    }

    // Epilogue
    float4 bvec = *(const float4*)(bias + col0 + tx * 4);
    #pragma unroll
    for (int i = 0; i < 8; i++) {
        int grow = row0 + ty * 8 + i;
        if (grow >= M) continue;
        float4 r;
        r.x = acc[i][0] + bvec.x;
        r.y = acc[i][1] + bvec.y;
        r.z = acc[i][2] + bvec.z;
        r.w = acc[i][3] + bvec.w;
        if (ACT == 0) {
            r.x = fmaxf(r.x, 0.f); r.y = fmaxf(r.y, 0.f);
            r.z = fmaxf(r.z, 0.f); r.w = fmaxf(r.w, 0.f);
        } else {
            r.x = 1.0f / (1.0f + expf(-r.x));
            r.y = 1.0f / (1.0f + expf(-r.y));
            r.z = 1.0f / (1.0f + expf(-r.z));
            r.w = 1.0f / (1.0f + expf(-r.w));
        }
        *(float4*)(C + (size_t)grow * N + col0 + tx * 4) = r;
    }
}

// ---------------- launch -----------------------------------------------------

extern "C" void kernel_launch(void* const* d_in, const int* in_sizes, int n_in,
                              void* d_out, int out_size) {
    const float* x    = (const float*)d_in[0];
    const float* W1l  = (const float*)d_in[1];
    const float* b1   = (const float*)d_in[2];
    const float* W1r  = (const float*)d_in[3];
    const float* W2l  = (const float*)d_in[4];
    const float* b2   = (const float*)d_in[5];
    const float* W2r  = (const float*)d_in[6];
    const int*   src1 = (const int*)d_in[7];
    const int*   dst1 = (const int*)d_in[8];
    const int*   src2 = (const int*)d_in[9];
    const int*   dst2 = (const int*)d_in[10];
    float* out = (float*)d_out;

    void *p_aggr1, *p_h, *p_aggr2, *p_cnt1, *p_cnt2, *p_inv1, *p_inv2;
    cudaGetSymbolAddress(&p_aggr1, g_aggr1);
    cudaGetSymbolAddress(&p_h,     g_h);
    cudaGetSymbolAddress(&p_aggr2, g_aggr2);
    cudaGetSymbolAddress(&p_cnt1,  g_cnt1);
    cudaGetSymbolAddress(&p_cnt2,  g_cnt2);
    cudaGetSymbolAddress(&p_inv1,  g_inv1);
    cudaGetSymbolAddress(&p_inv2,  g_inv2);

    float* aggr1 = (float*)p_aggr1;
    float* h     = (float*)p_h;
    float* aggr2 = (float*)p_aggr2;
    int*   cnt1  = (int*)p_cnt1;
    int*   cnt2  = (int*)p_cnt2;
    float* inv1  = (float*)p_inv1;
    float* inv2  = (float*)p_inv2;

    // Zero accumulators + counts (graph-capturable memset nodes)
    cudaMemsetAsync(aggr1, 0, (size_t)N1c * Dc * sizeof(float), 0);
    cudaMemsetAsync(aggr2, 0, (size_t)N2c * Dc * sizeof(float), 0);
    cudaMemsetAsync(cnt1,  0, (size_t)N1c * sizeof(int), 0);
    cudaMemsetAsync(cnt2,  0, (size_t)N2c * sizeof(int), 0);

    // ---- Layer 1 ----
    count_kernel<<<(E1c + 255) / 256, 256>>>(dst1, cnt1, E1c);
    inv_kernel<<<(N1c + 255) / 256, 256>>>(cnt1, inv1, N1c);
    {
        long long warps = E1c;
        int blocks = (int)((warps * 32 + 255) / 256);
        scatter_kernel<<<blocks, 256>>>(x, src1, dst1, aggr1, E1c);
    }
    {
        dim3 grid((N1c + 127) / 128, Dc / 64);
        gemm_fused<0><<<grid, 256>>>(aggr1, inv1, x, W1l, W1r, b1, h, N1c, Dc);
    }

    // ---- Layer 2 ----
    count_kernel<<<(E2c + 255) / 256, 256>>>(dst2, cnt2, E2c);
    inv_kernel<<<(N2c + 255) / 256, 256>>>(cnt2, inv2, N2c);
    {
        long long warps = E2c;
        int blocks = (int)((warps * 32 + 255) / 256);
        scatter_kernel<<<blocks, 256>>>(h, src2, dst2, aggr2, E2c);
    }
    {
        dim3 grid((N2c + 127) / 128, DOUTc / 64);
        gemm_fused<1><<<grid, 256>>>(aggr2, inv2, h, W2l, W2r, b2, out, N2c, DOUTc);
    }
}

// round 3
// speedup vs baseline: 1.4311x; 1.4311x over previous
#include <cuda_runtime.h>
#include <cuda_bf16.h>
#include <cstdint>
#include <math.h>

// Problem constants
#define N0c 100000
#define N1c 40000
#define N2c 10000
#define E1c 640000
#define E2c 160000
#define Dc  256
#define DOUTc 128

// ---------------- scratch (device globals) -----------------------------------
__device__ float g_aggr1[(size_t)N1c * Dc];
__device__ float g_h[(size_t)N1c * Dc];
__device__ float g_aggr2[(size_t)N2c * Dc];
__device__ int   g_cnt1[N1c];
__device__ int   g_cnt2[N2c];
__device__ float g_inv1[N1c];
__device__ float g_inv2[N2c];

// bf16 split buffers: A = [aggr*inv | x]  (M x 512), Wt = W^T ([N x 512])
__device__ __nv_bfloat16 g_A1h[(size_t)N1c * 512];
__device__ __nv_bfloat16 g_A1l[(size_t)N1c * 512];
__device__ __nv_bfloat16 g_A2h[(size_t)N2c * 512];
__device__ __nv_bfloat16 g_A2l[(size_t)N2c * 512];
__device__ __nv_bfloat16 g_W1h[(size_t)Dc * 512];
__device__ __nv_bfloat16 g_W1lo[(size_t)Dc * 512];
__device__ __nv_bfloat16 g_W2h[(size_t)DOUTc * 512];
__device__ __nv_bfloat16 g_W2lo[(size_t)DOUTc * 512];

// ---------------- PTX helpers ---------------------------------------------------

__device__ __forceinline__ uint32_t smem_u32(const void* p) {
    uint32_t a;
    asm("{ .reg .u64 t; cvta.to.shared.u64 t, %1; cvt.u32.u64 %0, t; }" : "=r"(a) : "l"(p));
    return a;
}

__device__ __forceinline__ void cp16(uint32_t dst, const void* src, uint32_t sz) {
    asm volatile("cp.async.ca.shared.global [%0], [%1], 16, %2;"
                 :: "r"(dst), "l"(src), "r"(sz) : "memory");
}
__device__ __forceinline__ void cp_commit() {
    asm volatile("cp.async.commit_group;" ::: "memory");
}
template <int N>
__device__ __forceinline__ void cp_wait() {
    asm volatile("cp.async.wait_group %0;" :: "n"(N) : "memory");
}

__device__ __forceinline__ void mma16816(float* c, const uint32_t* a, const uint32_t* b) {
    asm volatile(
        "mma.sync.aligned.m16n8k16.row.col.f32.bf16.bf16.f32 "
        "{%0,%1,%2,%3}, {%4,%5,%6,%7}, {%8,%9}, {%0,%1,%2,%3};"
        : "+f"(c[0]), "+f"(c[1]), "+f"(c[2]), "+f"(c[3])
        : "r"(a[0]), "r"(a[1]), "r"(a[2]), "r"(a[3]), "r"(b[0]), "r"(b[1]));
}

// ---------------- small kernels --------------------------------------------------

__global__ void count_kernel(const int* __restrict__ dst, int* __restrict__ cnt, int E) {
    int i = blockIdx.x * blockDim.x + threadIdx.x;
    if (i < E) atomicAdd(&cnt[dst[i]], 1);
}

__global__ void inv_kernel(const int* __restrict__ cnt, float* __restrict__ inv, int n) {
    int i = blockIdx.x * blockDim.x + threadIdx.x;
    if (i < n) inv[i] = 1.0f / (float)max(cnt[i], 1);
}

__global__ void scatter_kernel(const float* __restrict__ X, const int* __restrict__ src,
                               const int* __restrict__ dst, float* __restrict__ out, int E) {
    int gw   = (blockIdx.x * blockDim.x + threadIdx.x) >> 5;
    int lane = threadIdx.x & 31;
    if (gw >= E) return;
    int s = src[gw];
    int d = dst[gw];
    const float4* xr = (const float4*)(X + (size_t)s * Dc);
    float4*       o  = (float4*)(out + (size_t)d * Dc);
    float4 v0 = __ldg(&xr[lane]);
    float4 v1 = __ldg(&xr[lane + 32]);
    atomicAdd(&o[lane], v0);
    atomicAdd(&o[lane + 32], v1);
}

// Build A = [aggr*inv | xsrc] split into bf16 hi/lo, row-major M x 512.
__global__ void convertA_kernel(const float* __restrict__ aggr, const float* __restrict__ inv,
                                const float* __restrict__ xsrc,
                                __nv_bfloat16* __restrict__ Ah, __nv_bfloat16* __restrict__ Al,
                                int M) {
    int idx = blockIdx.x * blockDim.x + threadIdx.x;
    int total = M * 128;
    if (idx >= total) return;
    int row = idx >> 7;
    int col = (idx & 127) * 4;
    float4 v;
    if (col < 256) {
        v = *(const float4*)(aggr + (size_t)row * 256 + col);
        float s = inv[row];
        v.x *= s; v.y *= s; v.z *= s; v.w *= s;
    } else {
        v = *(const float4*)(xsrc + (size_t)row * 256 + (col - 256));
    }
    float f[4] = {v.x, v.y, v.z, v.w};
    __nv_bfloat16 hi[4], lo[4];
    #pragma unroll
    for (int j = 0; j < 4; j++) {
        hi[j] = __float2bfloat16(f[j]);
        lo[j] = __float2bfloat16(f[j] - __bfloat162float(hi[j]));
    }
    __nv_bfloat162* ph = (__nv_bfloat162*)(Ah + (size_t)row * 512 + col);
    __nv_bfloat162* pl = (__nv_bfloat162*)(Al + (size_t)row * 512 + col);
    ph[0] = __nv_bfloat162(hi[0], hi[1]);
    ph[1] = __nv_bfloat162(hi[2], hi[3]);
    pl[0] = __nv_bfloat162(lo[0], lo[1]);
    pl[1] = __nv_bfloat162(lo[2], lo[3]);
}

// Build Wt[n][k] = (k<256 ? Wl[k][n] : Wr[k-256][n]) split into bf16 hi/lo. [NT x 512]
__global__ void convertW_kernel(const float* __restrict__ Wl, const float* __restrict__ Wr,
                                __nv_bfloat16* __restrict__ Wh, __nv_bfloat16* __restrict__ Wlo,
                                int NT) {
    int idx = blockIdx.x * blockDim.x + threadIdx.x;
    if (idx >= NT * 512) return;
    int n = idx >> 9;
    int k = idx & 511;
    float v = (k < 256) ? Wl[(size_t)k * NT + n] : Wr[(size_t)(k - 256) * NT + n];
    __nv_bfloat16 hi = __float2bfloat16(v);
    __nv_bfloat16 lo = __float2bfloat16(v - __bfloat162float(hi));
    Wh[(size_t)n * 512 + k]  = hi;
    Wlo[(size_t)n * 512 + k] = lo;
}

// ---------------- mma.sync bf16 3-split GEMM -------------------------------------
// C[M x NTOT] = act( Ah@Bh^T + Ah@Bl^T + Al@Bh^T + bias )
// A: M x 512 bf16 (hi/lo), B: NTOT x 512 bf16 (hi/lo, = W^T). CTA tile 128x128.
// SMEM: padded rows, stride 40 bf16 (80 B) -> conflict-free fragment loads.
// Double-buffered cp.async pipeline over 16 chunks of BK=32.

#define SPAD 40                       // smem row stride in bf16 elems
#define MAT_BYTES (128 * SPAD * 2)    // 10240 B per matrix tile
#define STAGE_BYTES (4 * MAT_BYTES)   // Ah, Al, Bh, Bl
#define GEMM_SMEM (2 * STAGE_BYTES)   // 81920 B

template <int NTOT, int ACT>
__global__ void __launch_bounds__(256, 1)
gemm_mma(const __nv_bfloat16* __restrict__ Ah, const __nv_bfloat16* __restrict__ Al,
         const __nv_bfloat16* __restrict__ Bh, const __nv_bfloat16* __restrict__ Bl,
         const float* __restrict__ bias, float* __restrict__ C, int M)
{
    extern __shared__ char smem[];
    const uint32_t sbase = smem_u32(smem);
    const int tid  = threadIdx.x;
    const int wid  = tid >> 5;
    const int lane = tid & 31;
    const int wm   = wid >> 2;          // 0..1  -> 64-row slice
    const int wn   = wid & 3;           // 0..3  -> 32-col slice
    const int g    = lane >> 2;         // group id 0..7
    const int t    = lane & 3;          // thread-in-group

    const int row0 = blockIdx.x * 128;
    const int col0 = blockIdx.y * 128;

    float acc[4][4][4];
    #pragma unroll
    for (int i = 0; i < 4; i++)
        #pragma unroll
        for (int j = 0; j < 4; j++)
            #pragma unroll
            for (int q = 0; q < 4; q++) acc[i][j][q] = 0.0f;

    // ------- stage loader: 2048 x 16B cp.async (8 per thread) -------
    auto load_stage = [&](int s, int k0) {
        uint32_t base = sbase + s * STAGE_BYTES;
        #pragma unroll
        for (int q8 = 0; q8 < 8; q8++) {
            int idx  = q8 * 256 + tid;         // 0..2047
            int mat  = idx >> 9;               // 0:Ah 1:Al 2:Bh 3:Bl
            int slot = idx & 511;
            int row  = slot >> 2;
            int quar = slot & 3;
            uint32_t dst = base + mat * MAT_BYTES + row * (SPAD * 2) + quar * 16;
            if (mat < 2) {
                int grow = row0 + row;
                int srow = grow < M ? grow : (M - 1);
                const __nv_bfloat16* src =
                    (mat == 0 ? Ah : Al) + (size_t)srow * 512 + k0 + quar * 8;
                cp16(dst, src, grow < M ? 16u : 0u);
            } else {
                const __nv_bfloat16* src =
                    (mat == 2 ? Bh : Bl) + (size_t)(col0 + row) * 512 + k0 + quar * 8;
                cp16(dst, src, 16u);
            }
        }
    };

    load_stage(0, 0);
    cp_commit();

    #pragma unroll 1
    for (int c = 0; c < 16; c++) {
        if (c < 15) {
            load_stage((c + 1) & 1, (c + 1) * 32);
            cp_commit();
            cp_wait<1>();
        } else {
            cp_wait<0>();
        }
        __syncthreads();

        const char* st  = smem + (c & 1) * STAGE_BYTES;
        const char* pAh = st;
        const char* pAl = st + MAT_BYTES;
        const char* pBh = st + 2 * MAT_BYTES;
        const char* pBl = st + 3 * MAT_BYTES;

        #pragma unroll
        for (int kk = 0; kk < 32; kk += 16) {
            uint32_t ah[4][4], al[4][4], bh[4][2], bl[4][2];
            #pragma unroll
            for (int i = 0; i < 4; i++) {
                int r = wm * 64 + i * 16 + g;
                int cb0 = (kk + 2 * t) * 2;         // byte offset of col pair
                const char* base0 = pAh + r * (SPAD * 2);
                const char* base1 = pAh + (r + 8) * (SPAD * 2);
                ah[i][0] = *(const uint32_t*)(base0 + cb0);
                ah[i][1] = *(const uint32_t*)(base1 + cb0);
                ah[i][2] = *(const uint32_t*)(base0 + cb0 + 16);
                ah[i][3] = *(const uint32_t*)(base1 + cb0 + 16);
                const char* base0l = pAl + r * (SPAD * 2);
                const char* base1l = pAl + (r + 8) * (SPAD * 2);
                al[i][0] = *(const uint32_t*)(base0l + cb0);
                al[i][1] = *(const uint32_t*)(base1l + cb0);
                al[i][2] = *(const uint32_t*)(base0l + cb0 + 16);
                al[i][3] = *(const uint32_t*)(base1l + cb0 + 16);
            }
            #pragma unroll
            for (int j = 0; j < 4; j++) {
                int n = wn * 32 + j * 8 + g;
                int cb0 = (kk + 2 * t) * 2;
                bh[j][0] = *(const uint32_t*)(pBh + n * (SPAD * 2) + cb0);
                bh[j][1] = *(const uint32_t*)(pBh + n * (SPAD * 2) + cb0 + 16);
                bl[j][0] = *(const uint32_t*)(pBl + n * (SPAD * 2) + cb0);
                bl[j][1] = *(const uint32_t*)(pBl + n * (SPAD * 2) + cb0 + 16);
            }
            #pragma unroll
            for (int i = 0; i < 4; i++)
                #pragma unroll
                for (int j = 0; j < 4; j++) {
                    mma16816(acc[i][j], ah[i], bh[j]);
                    mma16816(acc[i][j], ah[i], bl[j]);
                    mma16816(acc[i][j], al[i], bh[j]);
                }
        }
        __syncthreads();
    }

    // ------- epilogue -------
    #pragma unroll
    for (int j = 0; j < 4; j++) {
        int cidx = col0 + wn * 32 + j * 8 + 2 * t;
        float bx = bias[cidx], by = bias[cidx + 1];
        #pragma unroll
        for (int i = 0; i < 4; i++) {
            int r = row0 + wm * 64 + i * 16 + g;
            float v0 = acc[i][j][0] + bx;
            float v1 = acc[i][j][1] + by;
            float v2 = acc[i][j][2] + bx;
            float v3 = acc[i][j][3] + by;
            if (ACT == 0) {
                v0 = fmaxf(v0, 0.f); v1 = fmaxf(v1, 0.f);
                v2 = fmaxf(v2, 0.f); v3 = fmaxf(v3, 0.f);
            } else {
                v0 = 1.0f / (1.0f + expf(-v0));
                v1 = 1.0f / (1.0f + expf(-v1));
                v2 = 1.0f / (1.0f + expf(-v2));
                v3 = 1.0f / (1.0f + expf(-v3));
            }
            if (r < M)     *(float2*)(C + (size_t)r * NTOT + cidx)       = make_float2(v0, v1);
            if (r + 8 < M) *(float2*)(C + (size_t)(r + 8) * NTOT + cidx) = make_float2(v2, v3);
        }
    }
}

// ---------------- launch ----------------------------------------------------------

extern "C" void kernel_launch(void* const* d_in, const int* in_sizes, int n_in,
                              void* d_out, int out_size) {
    const float* x    = (const float*)d_in[0];
    const float* W1l  = (const float*)d_in[1];
    const float* b1   = (const float*)d_in[2];
    const float* W1r  = (const float*)d_in[3];
    const float* W2l  = (const float*)d_in[4];
    const float* b2   = (const float*)d_in[5];
    const float* W2r  = (const float*)d_in[6];
    const int*   src1 = (const int*)d_in[7];
    const int*   dst1 = (const int*)d_in[8];
    const int*   src2 = (const int*)d_in[9];
    const int*   dst2 = (const int*)d_in[10];
    float* out = (float*)d_out;

    void *p;
    float *aggr1, *h, *aggr2, *inv1, *inv2;
    int *cnt1, *cnt2;
    __nv_bfloat16 *A1h, *A1l, *A2h, *A2l, *W1h_, *W1lo_, *W2h_, *W2lo_;
    cudaGetSymbolAddress(&p, g_aggr1); aggr1 = (float*)p;
    cudaGetSymbolAddress(&p, g_h);     h     = (float*)p;
    cudaGetSymbolAddress(&p, g_aggr2); aggr2 = (float*)p;
    cudaGetSymbolAddress(&p, g_cnt1);  cnt1  = (int*)p;
    cudaGetSymbolAddress(&p, g_cnt2);  cnt2  = (int*)p;
    cudaGetSymbolAddress(&p, g_inv1);  inv1  = (float*)p;
    cudaGetSymbolAddress(&p, g_inv2);  inv2  = (float*)p;
    cudaGetSymbolAddress(&p, g_A1h);   A1h   = (__nv_bfloat16*)p;
    cudaGetSymbolAddress(&p, g_A1l);   A1l   = (__nv_bfloat16*)p;
    cudaGetSymbolAddress(&p, g_A2h);   A2h   = (__nv_bfloat16*)p;
    cudaGetSymbolAddress(&p, g_A2l);   A2l   = (__nv_bfloat16*)p;
    cudaGetSymbolAddress(&p, g_W1h);   W1h_  = (__nv_bfloat16*)p;
    cudaGetSymbolAddress(&p, g_W1lo);  W1lo_ = (__nv_bfloat16*)p;
    cudaGetSymbolAddress(&p, g_W2h);   W2h_  = (__nv_bfloat16*)p;
    cudaGetSymbolAddress(&p, g_W2lo);  W2lo_ = (__nv_bfloat16*)p;

    cudaFuncSetAttribute(gemm_mma<256, 0>, cudaFuncAttributeMaxDynamicSharedMemorySize, GEMM_SMEM);
    cudaFuncSetAttribute(gemm_mma<128, 1>, cudaFuncAttributeMaxDynamicSharedMemorySize, GEMM_SMEM);

    cudaMemsetAsync(aggr1, 0, (size_t)N1c * Dc * sizeof(float), 0);
    cudaMemsetAsync(aggr2, 0, (size_t)N2c * Dc * sizeof(float), 0);
    cudaMemsetAsync(cnt1,  0, (size_t)N1c * sizeof(int), 0);
    cudaMemsetAsync(cnt2,  0, (size_t)N2c * sizeof(int), 0);

    // ---- Layer 1 ----
    count_kernel<<<(E1c + 255) / 256, 256>>>(dst1, cnt1, E1c);
    inv_kernel<<<(N1c + 255) / 256, 256>>>(cnt1, inv1, N1c);
    scatter_kernel<<<(E1c * 32 + 255) / 256, 256>>>(x, src1, dst1, aggr1, E1c);

    convertW_kernel<<<(Dc * 512 + 255) / 256, 256>>>(W1l, W1r, W1h_, W1lo_, Dc);
    convertA_kernel<<<(N1c * 128 + 255) / 256, 256>>>(aggr1, inv1, x, A1h, A1l, N1c);

    {
        dim3 grid((N1c + 127) / 128, 2);
        gemm_mma<256, 0><<<grid, 256, GEMM_SMEM>>>(A1h, A1l, W1h_, W1lo_, b1, h, N1c);
    }

    // ---- Layer 2 ----
    count_kernel<<<(E2c + 255) / 256, 256>>>(dst2, cnt2, E2c);
    inv_kernel<<<(N2c + 255) / 256, 256>>>(cnt2, inv2, N2c);
    scatter_kernel<<<(E2c * 32 + 255) / 256, 256>>>(h, src2, dst2, aggr2, E2c);

    convertW_kernel<<<(DOUTc * 512 + 255) / 256, 256>>>(W2l, W2r, W2h_, W2lo_, DOUTc);
    convertA_kernel<<<(N2c * 128 + 255) / 256, 256>>>(aggr2, inv2, h, A2h, A2l, N2c);

    {
        dim3 grid((N2c + 127) / 128, 1);
        gemm_mma<128, 1><<<grid, 256, GEMM_SMEM>>>(A2h, A2l, W2h_, W2lo_, b2, out, N2c);
    }
}

// round 4
// speedup vs baseline: 1.6811x; 1.1747x over previous
#include <cuda_runtime.h>
#include <cuda_bf16.h>
#include <cstdint>
#include <math.h>

// Problem constants
#define N0c 100000
#define N1c 40000
#define N2c 10000
#define E1c 640000
#define E2c 160000
#define Dc  256
#define DOUTc 128

// ---------------- scratch (device globals) -----------------------------------
__device__ float g_h[(size_t)N1c * Dc];
__device__ int   g_cnt1[N1c];
__device__ int   g_cnt2[N2c];
__device__ int   g_offs1[N1c + 1];
__device__ int   g_offs2[N2c + 1];
__device__ int   g_cur1[N1c];
__device__ int   g_cur2[N2c];
__device__ int   g_eid1[E1c];
__device__ int   g_eid2[E2c];

// bf16 split buffers: A = [aggr*inv | self]  (M x 512), Wt = W^T ([N x 512])
__device__ __nv_bfloat16 g_A1h[(size_t)N1c * 512];
__device__ __nv_bfloat16 g_A1l[(size_t)N1c * 512];
__device__ __nv_bfloat16 g_A2h[(size_t)N2c * 512];
__device__ __nv_bfloat16 g_A2l[(size_t)N2c * 512];
__device__ __nv_bfloat16 g_W1h[(size_t)Dc * 512];
__device__ __nv_bfloat16 g_W1lo[(size_t)Dc * 512];
__device__ __nv_bfloat16 g_W2h[(size_t)DOUTc * 512];
__device__ __nv_bfloat16 g_W2lo[(size_t)DOUTc * 512];

// ---------------- PTX helpers ---------------------------------------------------

__device__ __forceinline__ uint32_t smem_u32(const void* p) {
    uint32_t a;
    asm("{ .reg .u64 t; cvta.to.shared.u64 t, %1; cvt.u32.u64 %0, t; }" : "=r"(a) : "l"(p));
    return a;
}

__device__ __forceinline__ void cp16(uint32_t dst, const void* src, uint32_t sz) {
    asm volatile("cp.async.ca.shared.global [%0], [%1], 16, %2;"
                 :: "r"(dst), "l"(src), "r"(sz) : "memory");
}
__device__ __forceinline__ void cp_commit() {
    asm volatile("cp.async.commit_group;" ::: "memory");
}
template <int N>
__device__ __forceinline__ void cp_wait() {
    asm volatile("cp.async.wait_group %0;" :: "n"(N) : "memory");
}

__device__ __forceinline__ void mma16816(float* c, const uint32_t* a, const uint32_t* b) {
    asm volatile(
        "mma.sync.aligned.m16n8k16.row.col.f32.bf16.bf16.f32 "
        "{%0,%1,%2,%3}, {%4,%5,%6,%7}, {%8,%9}, {%0,%1,%2,%3};"
        : "+f"(c[0]), "+f"(c[1]), "+f"(c[2]), "+f"(c[3])
        : "r"(a[0]), "r"(a[1]), "r"(a[2]), "r"(a[3]), "r"(b[0]), "r"(b[1]));
}

// ---------------- CSR build kernels -----------------------------------------------

__global__ void count_kernel(const int* __restrict__ dst, int* __restrict__ cnt, int E) {
    int i = blockIdx.x * blockDim.x + threadIdx.x;
    if (i < E) atomicAdd(&cnt[dst[i]], 1);
}

// Single-block exclusive scan over n counts; writes offs[0..n] and cursor[0..n-1].
__global__ void scan_kernel(const int* __restrict__ cnt, int* __restrict__ offs,
                            int* __restrict__ cursor, int n) {
    __shared__ int warpsums[32];
    __shared__ int s_carry;
    const int lane = threadIdx.x & 31;
    const int wid  = threadIdx.x >> 5;
    const int nw   = blockDim.x >> 5;
    if (threadIdx.x == 0) s_carry = 0;
    __syncthreads();
    for (int base = 0; base < n; base += blockDim.x) {
        int i = base + threadIdx.x;
        int v = (i < n) ? cnt[i] : 0;
        int carry = s_carry;
        int x = v;
        #pragma unroll
        for (int o = 1; o < 32; o <<= 1) {
            int y = __shfl_up_sync(0xFFFFFFFFu, x, o);
            if (lane >= o) x += y;
        }
        if (lane == 31) warpsums[wid] = x;
        __syncthreads();
        if (wid == 0) {
            int w = (lane < nw) ? warpsums[lane] : 0;
            #pragma unroll
            for (int o = 1; o < 32; o <<= 1) {
                int y = __shfl_up_sync(0xFFFFFFFFu, w, o);
                if (lane >= o) w += y;
            }
            warpsums[lane] = w;
        }
        __syncthreads();
        int incl = x + (wid > 0 ? warpsums[wid - 1] : 0) + carry;
        if (i < n) { offs[i] = incl - v; cursor[i] = incl - v; }
        __syncthreads();
        if (threadIdx.x == blockDim.x - 1) s_carry = incl;
        __syncthreads();
    }
    if (threadIdx.x == 0) offs[n] = s_carry;
}

__global__ void fill_kernel(const int* __restrict__ src, const int* __restrict__ dst,
                            int* __restrict__ cursor, int* __restrict__ eid, int E) {
    int i = blockIdx.x * blockDim.x + threadIdx.x;
    if (i < E) {
        int d = dst[i];
        int pos = atomicAdd(&cursor[d], 1);
        eid[pos] = src[i];
    }
}

// ---------------- fused gather-mean + bf16 split ----------------------------------

__device__ __forceinline__ void split4_store(__nv_bfloat16* __restrict__ Ah,
                                             __nv_bfloat16* __restrict__ Al,
                                             size_t row, int col, float4 v) {
    __nv_bfloat16 h0 = __float2bfloat16(v.x);
    __nv_bfloat16 h1 = __float2bfloat16(v.y);
    __nv_bfloat16 h2 = __float2bfloat16(v.z);
    __nv_bfloat16 h3 = __float2bfloat16(v.w);
    __nv_bfloat16 l0 = __float2bfloat16(v.x - __bfloat162float(h0));
    __nv_bfloat16 l1 = __float2bfloat16(v.y - __bfloat162float(h1));
    __nv_bfloat16 l2 = __float2bfloat16(v.z - __bfloat162float(h2));
    __nv_bfloat16 l3 = __float2bfloat16(v.w - __bfloat162float(h3));
    uint2 uh, ul;
    uh.x = (uint32_t)__bfloat16_as_ushort(h0) | ((uint32_t)__bfloat16_as_ushort(h1) << 16);
    uh.y = (uint32_t)__bfloat16_as_ushort(h2) | ((uint32_t)__bfloat16_as_ushort(h3) << 16);
    ul.x = (uint32_t)__bfloat16_as_ushort(l0) | ((uint32_t)__bfloat16_as_ushort(l1) << 16);
    ul.y = (uint32_t)__bfloat16_as_ushort(l2) | ((uint32_t)__bfloat16_as_ushort(l3) << 16);
    *(uint2*)(Ah + row * 512 + col) = uh;
    *(uint2*)(Al + row * 512 + col) = ul;
}

// One warp per dst row: mean over CSR neighbor rows of X, plus self row copy;
// writes A = [mean | self] split into bf16 hi/lo.
__global__ void gather_convert_kernel(const float* __restrict__ X,
                                      const float* __restrict__ Self,
                                      const int* __restrict__ offs,
                                      const int* __restrict__ eid,
                                      __nv_bfloat16* __restrict__ Ah,
                                      __nv_bfloat16* __restrict__ Al, int Ndst) {
    int w    = (blockIdx.x * blockDim.x + threadIdx.x) >> 5;
    int lane = threadIdx.x & 31;
    if (w >= Ndst) return;
    int beg = offs[w], end = offs[w + 1];

    float4 s0 = make_float4(0.f, 0.f, 0.f, 0.f);
    float4 s1 = s0;
    int e = beg;
    for (; e + 1 < end; e += 2) {
        int i0 = eid[e], i1 = eid[e + 1];
        const float4* r0 = (const float4*)(X + (size_t)i0 * Dc);
        const float4* r1 = (const float4*)(X + (size_t)i1 * Dc);
        float4 a0 = __ldg(&r0[lane]);
        float4 a1 = __ldg(&r0[lane + 32]);
        float4 b0 = __ldg(&r1[lane]);
        float4 b1 = __ldg(&r1[lane + 32]);
        s0.x += a0.x + b0.x; s0.y += a0.y + b0.y; s0.z += a0.z + b0.z; s0.w += a0.w + b0.w;
        s1.x += a1.x + b1.x; s1.y += a1.y + b1.y; s1.z += a1.z + b1.z; s1.w += a1.w + b1.w;
    }
    if (e < end) {
        int i0 = eid[e];
        const float4* r0 = (const float4*)(X + (size_t)i0 * Dc);
        float4 a0 = __ldg(&r0[lane]);
        float4 a1 = __ldg(&r0[lane + 32]);
        s0.x += a0.x; s0.y += a0.y; s0.z += a0.z; s0.w += a0.w;
        s1.x += a1.x; s1.y += a1.y; s1.z += a1.z; s1.w += a1.w;
    }
    float invd = 1.0f / (float)max(end - beg, 1);
    s0.x *= invd; s0.y *= invd; s0.z *= invd; s0.w *= invd;
    s1.x *= invd; s1.y *= invd; s1.z *= invd; s1.w *= invd;

    const float4* sr = (const float4*)(Self + (size_t)w * Dc);
    float4 t0 = __ldg(&sr[lane]);
    float4 t1 = __ldg(&sr[lane + 32]);

    split4_store(Ah, Al, (size_t)w, 4 * lane,        s0);
    split4_store(Ah, Al, (size_t)w, 128 + 4 * lane,  s1);
    split4_store(Ah, Al, (size_t)w, 256 + 4 * lane,  t0);
    split4_store(Ah, Al, (size_t)w, 384 + 4 * lane,  t1);
}

// Build Wt[n][k] = (k<256 ? Wl[k][n] : Wr[k-256][n]) split into bf16 hi/lo. [NT x 512]
__global__ void convertW_kernel(const float* __restrict__ Wl, const float* __restrict__ Wr,
                                __nv_bfloat16* __restrict__ Wh, __nv_bfloat16* __restrict__ Wlo,
                                int NT) {
    int idx = blockIdx.x * blockDim.x + threadIdx.x;
    if (idx >= NT * 512) return;
    int n = idx >> 9;
    int k = idx & 511;
    float v = (k < 256) ? Wl[(size_t)k * NT + n] : Wr[(size_t)(k - 256) * NT + n];
    __nv_bfloat16 hi = __float2bfloat16(v);
    __nv_bfloat16 lo = __float2bfloat16(v - __bfloat162float(hi));
    Wh[(size_t)n * 512 + k]  = hi;
    Wlo[(size_t)n * 512 + k] = lo;
}

// ---------------- mma.sync bf16 3-split GEMM (unchanged from R3) -------------------

#define SPAD 40
#define MAT_BYTES (128 * SPAD * 2)
#define STAGE_BYTES (4 * MAT_BYTES)
#define GEMM_SMEM (2 * STAGE_BYTES)

template <int NTOT, int ACT>
__global__ void __launch_bounds__(256, 1)
gemm_mma(const __nv_bfloat16* __restrict__ Ah, const __nv_bfloat16* __restrict__ Al,
         const __nv_bfloat16* __restrict__ Bh, const __nv_bfloat16* __restrict__ Bl,
         const float* __restrict__ bias, float* __restrict__ C, int M)
{
    extern __shared__ char smem[];
    const uint32_t sbase = smem_u32(smem);
    const int tid  = threadIdx.x;
    const int wid  = tid >> 5;
    const int lane = tid & 31;
    const int wm   = wid >> 2;
    const int wn   = wid & 3;
    const int g    = lane >> 2;
    const int t    = lane & 3;

    const int row0 = blockIdx.x * 128;
    const int col0 = blockIdx.y * 128;

    float acc[4][4][4];
    #pragma unroll
    for (int i = 0; i < 4; i++)
        #pragma unroll
        for (int j = 0; j < 4; j++)
            #pragma unroll
            for (int q = 0; q < 4; q++) acc[i][j][q] = 0.0f;

    auto load_stage = [&](int s, int k0) {
        uint32_t base = sbase + s * STAGE_BYTES;
        #pragma unroll
        for (int q8 = 0; q8 < 8; q8++) {
            int idx  = q8 * 256 + tid;
            int mat  = idx >> 9;
            int slot = idx & 511;
            int row  = slot >> 2;
            int quar = slot & 3;
            uint32_t dst = base + mat * MAT_BYTES + row * (SPAD * 2) + quar * 16;
            if (mat < 2) {
                int grow = row0 + row;
                int srow = grow < M ? grow : (M - 1);
                const __nv_bfloat16* src =
                    (mat == 0 ? Ah : Al) + (size_t)srow * 512 + k0 + quar * 8;
                cp16(dst, src, grow < M ? 16u : 0u);
            } else {
                const __nv_bfloat16* src =
                    (mat == 2 ? Bh : Bl) + (size_t)(col0 + row) * 512 + k0 + quar * 8;
                cp16(dst, src, 16u);
            }
        }
    };

    load_stage(0, 0);
    cp_commit();

    #pragma unroll 1
    for (int c = 0; c < 16; c++) {
        if (c < 15) {
            load_stage((c + 1) & 1, (c + 1) * 32);
            cp_commit();
            cp_wait<1>();
        } else {
            cp_wait<0>();
        }
        __syncthreads();

        const char* st  = smem + (c & 1) * STAGE_BYTES;
        const char* pAh = st;
        const char* pAl = st + MAT_BYTES;
        const char* pBh = st + 2 * MAT_BYTES;
        const char* pBl = st + 3 * MAT_BYTES;

        #pragma unroll
        for (int kk = 0; kk < 32; kk += 16) {
            uint32_t ah[4][4], al[4][4], bh[4][2], bl[4][2];
            #pragma unroll
            for (int i = 0; i < 4; i++) {
                int r = wm * 64 + i * 16 + g;
                int cb0 = (kk + 2 * t) * 2;
                const char* base0 = pAh + r * (SPAD * 2);
                const char* base1 = pAh + (r + 8) * (SPAD * 2);
                ah[i][0] = *(const uint32_t*)(base0 + cb0);
                ah[i][1] = *(const uint32_t*)(base1 + cb0);
                ah[i][2] = *(const uint32_t*)(base0 + cb0 + 16);
                ah[i][3] = *(const uint32_t*)(base1 + cb0 + 16);
                const char* base0l = pAl + r * (SPAD * 2);
                const char* base1l = pAl + (r + 8) * (SPAD * 2);
                al[i][0] = *(const uint32_t*)(base0l + cb0);
                al[i][1] = *(const uint32_t*)(base1l + cb0);
                al[i][2] = *(const uint32_t*)(base0l + cb0 + 16);
                al[i][3] = *(const uint32_t*)(base1l + cb0 + 16);
            }
            #pragma unroll
            for (int j = 0; j < 4; j++) {
                int n = wn * 32 + j * 8 + g;
                int cb0 = (kk + 2 * t) * 2;
                bh[j][0] = *(const uint32_t*)(pBh + n * (SPAD * 2) + cb0);
                bh[j][1] = *(const uint32_t*)(pBh + n * (SPAD * 2) + cb0 + 16);
                bl[j][0] = *(const uint32_t*)(pBl + n * (SPAD * 2) + cb0);
                bl[j][1] = *(const uint32_t*)(pBl + n * (SPAD * 2) + cb0 + 16);
            }
            #pragma unroll
            for (int i = 0; i < 4; i++)
                #pragma unroll
                for (int j = 0; j < 4; j++) {
                    mma16816(acc[i][j], ah[i], bh[j]);
                    mma16816(acc[i][j], ah[i], bl[j]);
                    mma16816(acc[i][j], al[i], bh[j]);
                }
        }
        __syncthreads();
    }

    #pragma unroll
    for (int j = 0; j < 4; j++) {
        int cidx = col0 + wn * 32 + j * 8 + 2 * t;
        float bx = bias[cidx], by = bias[cidx + 1];
        #pragma unroll
        for (int i = 0; i < 4; i++) {
            int r = row0 + wm * 64 + i * 16 + g;
            float v0 = acc[i][j][0] + bx;
            float v1 = acc[i][j][1] + by;
            float v2 = acc[i][j][2] + bx;
            float v3 = acc[i][j][3] + by;
            if (ACT == 0) {
                v0 = fmaxf(v0, 0.f); v1 = fmaxf(v1, 0.f);
                v2 = fmaxf(v2, 0.f); v3 = fmaxf(v3, 0.f);
            } else {
                v0 = 1.0f / (1.0f + expf(-v0));
                v1 = 1.0f / (1.0f + expf(-v1));
                v2 = 1.0f / (1.0f + expf(-v2));
                v3 = 1.0f / (1.0f + expf(-v3));
            }
            if (r < M)     *(float2*)(C + (size_t)r * NTOT + cidx)       = make_float2(v0, v1);
            if (r + 8 < M) *(float2*)(C + (size_t)(r + 8) * NTOT + cidx) = make_float2(v2, v3);
        }
    }
}

// ---------------- launch ----------------------------------------------------------

extern "C" void kernel_launch(void* const* d_in, const int* in_sizes, int n_in,
                              void* d_out, int out_size) {
    const float* x    = (const float*)d_in[0];
    const float* W1l  = (const float*)d_in[1];
    const float* b1   = (const float*)d_in[2];
    const float* W1r  = (const float*)d_in[3];
    const float* W2l  = (const float*)d_in[4];
    const float* b2   = (const float*)d_in[5];
    const float* W2r  = (const float*)d_in[6];
    const int*   src1 = (const int*)d_in[7];
    const int*   dst1 = (const int*)d_in[8];
    const int*   src2 = (const int*)d_in[9];
    const int*   dst2 = (const int*)d_in[10];
    float* out = (float*)d_out;

    void *p;
    float *h;
    int *cnt1, *cnt2, *offs1, *offs2, *cur1, *cur2, *eid1, *eid2;
    __nv_bfloat16 *A1h, *A1l, *A2h, *A2l, *W1h_, *W1lo_, *W2h_, *W2lo_;
    cudaGetSymbolAddress(&p, g_h);     h     = (float*)p;
    cudaGetSymbolAddress(&p, g_cnt1);  cnt1  = (int*)p;
    cudaGetSymbolAddress(&p, g_cnt2);  cnt2  = (int*)p;
    cudaGetSymbolAddress(&p, g_offs1); offs1 = (int*)p;
    cudaGetSymbolAddress(&p, g_offs2); offs2 = (int*)p;
    cudaGetSymbolAddress(&p, g_cur1);  cur1  = (int*)p;
    cudaGetSymbolAddress(&p, g_cur2);  cur2  = (int*)p;
    cudaGetSymbolAddress(&p, g_eid1);  eid1  = (int*)p;
    cudaGetSymbolAddress(&p, g_eid2);  eid2  = (int*)p;
    cudaGetSymbolAddress(&p, g_A1h);   A1h   = (__nv_bfloat16*)p;
    cudaGetSymbolAddress(&p, g_A1l);   A1l   = (__nv_bfloat16*)p;
    cudaGetSymbolAddress(&p, g_A2h);   A2h   = (__nv_bfloat16*)p;
    cudaGetSymbolAddress(&p, g_A2l);   A2l   = (__nv_bfloat16*)p;
    cudaGetSymbolAddress(&p, g_W1h);   W1h_  = (__nv_bfloat16*)p;
    cudaGetSymbolAddress(&p, g_W1lo);  W1lo_ = (__nv_bfloat16*)p;
    cudaGetSymbolAddress(&p, g_W2h);   W2h_  = (__nv_bfloat16*)p;
    cudaGetSymbolAddress(&p, g_W2lo);  W2lo_ = (__nv_bfloat16*)p;

    cudaFuncSetAttribute(gemm_mma<256, 0>, cudaFuncAttributeMaxDynamicSharedMemorySize, GEMM_SMEM);
    cudaFuncSetAttribute(gemm_mma<128, 1>, cudaFuncAttributeMaxDynamicSharedMemorySize, GEMM_SMEM);

    cudaMemsetAsync(cnt1, 0, (size_t)N1c * sizeof(int), 0);
    cudaMemsetAsync(cnt2, 0, (size_t)N2c * sizeof(int), 0);

    // ---- Layer 1 ----
    count_kernel<<<(E1c + 255) / 256, 256>>>(dst1, cnt1, E1c);
    scan_kernel<<<1, 1024>>>(cnt1, offs1, cur1, N1c);
    fill_kernel<<<(E1c + 255) / 256, 256>>>(src1, dst1, cur1, eid1, E1c);
    convertW_kernel<<<(Dc * 512 + 255) / 256, 256>>>(W1l, W1r, W1h_, W1lo_, Dc);
    gather_convert_kernel<<<(N1c * 32 + 255) / 256, 256>>>(x, x, offs1, eid1, A1h, A1l, N1c);
    {
        dim3 grid((N1c + 127) / 128, 2);
        gemm_mma<256, 0><<<grid, 256, GEMM_SMEM>>>(A1h, A1l, W1h_, W1lo_, b1, h, N1c);
    }

    // ---- Layer 2 ----
    count_kernel<<<(E2c + 255) / 256, 256>>>(dst2, cnt2, E2c);
    scan_kernel<<<1, 1024>>>(cnt2, offs2, cur2, N2c);
    fill_kernel<<<(E2c + 255) / 256, 256>>>(src2, dst2, cur2, eid2, E2c);
    convertW_kernel<<<(DOUTc * 512 + 255) / 256, 256>>>(W2l, W2r, W2h_, W2lo_, DOUTc);
    gather_convert_kernel<<<(N2c * 32 + 255) / 256, 256>>>(h, h, offs2, eid2, A2h, A2l, N2c);
    {
        dim3 grid((N2c + 127) / 128, 1);
        gemm_mma<128, 1><<<grid, 256, GEMM_SMEM>>>(A2h, A2l, W2h_, W2lo_, b2, out, N2c);
    }
}

// round 5
// speedup vs baseline: 1.7886x; 1.0639x over previous
#include <cuda_runtime.h>
#include <cuda_bf16.h>
#include <cstdint>
#include <math.h>

// Problem constants
#define N0c 100000
#define N1c 40000
#define N2c 10000
#define E1c 640000
#define E2c 160000
#define Dc  256
#define DOUTc 128

#define GATHER1_BLOCKS (N1c / 8)          // 5000 (8 warps/block)
#define W1_BLOCKS      ((Dc * 512) / 256) // 512
#define W2_BLOCKS      ((DOUTc * 512) / 256) // 256

// ---------------- scratch (device globals) -----------------------------------
__device__ float g_h[(size_t)N1c * Dc];
__device__ int   g_cnt[N1c + N2c];        // contiguous: one memset
__device__ int   g_offs1[N1c + 1];
__device__ int   g_offs2[N2c + 1];
__device__ int   g_cur1[N1c];
__device__ int   g_cur2[N2c];
__device__ int   g_eid1[E1c];
__device__ int   g_eid2[E2c];

__device__ __nv_bfloat16 g_A1h[(size_t)N1c * 512];
__device__ __nv_bfloat16 g_A1l[(size_t)N1c * 512];
__device__ __nv_bfloat16 g_A2h[(size_t)N2c * 512];
__device__ __nv_bfloat16 g_A2l[(size_t)N2c * 512];
__device__ __nv_bfloat16 g_W1h[(size_t)Dc * 512];
__device__ __nv_bfloat16 g_W1lo[(size_t)Dc * 512];
__device__ __nv_bfloat16 g_W2h[(size_t)DOUTc * 512];
__device__ __nv_bfloat16 g_W2lo[(size_t)DOUTc * 512];

// ---------------- PTX helpers ---------------------------------------------------

__device__ __forceinline__ uint32_t smem_u32(const void* p) {
    uint32_t a;
    asm("{ .reg .u64 t; cvta.to.shared.u64 t, %1; cvt.u32.u64 %0, t; }" : "=r"(a) : "l"(p));
    return a;
}

__device__ __forceinline__ void cp16(uint32_t dst, const void* src, uint32_t sz) {
    asm volatile("cp.async.ca.shared.global [%0], [%1], 16, %2;"
                 :: "r"(dst), "l"(src), "r"(sz) : "memory");
}
__device__ __forceinline__ void cp_commit() {
    asm volatile("cp.async.commit_group;" ::: "memory");
}
template <int N>
__device__ __forceinline__ void cp_wait() {
    asm volatile("cp.async.wait_group %0;" :: "n"(N) : "memory");
}

__device__ __forceinline__ void mma16816(float* c, const uint32_t* a, const uint32_t* b) {
    asm volatile(
        "mma.sync.aligned.m16n8k16.row.col.f32.bf16.bf16.f32 "
        "{%0,%1,%2,%3}, {%4,%5,%6,%7}, {%8,%9}, {%0,%1,%2,%3};"
        : "+f"(c[0]), "+f"(c[1]), "+f"(c[2]), "+f"(c[3])
        : "r"(a[0]), "r"(a[1]), "r"(a[2]), "r"(a[3]), "r"(b[0]), "r"(b[1]));
}

// ---------------- CSR build (both layers fused) -----------------------------------

__global__ void count_both_kernel(const int* __restrict__ dst1, const int* __restrict__ dst2,
                                  int* __restrict__ cnt) {
    int i = blockIdx.x * blockDim.x + threadIdx.x;
    if (i < E1c) {
        atomicAdd(&cnt[dst1[i]], 1);
    } else if (i < E1c + E2c) {
        atomicAdd(&cnt[N1c + dst2[i - E1c]], 1);
    }
}

// grid=2 blocks: block 0 scans layer1 counts, block 1 scans layer2 counts.
__global__ void scan_both_kernel(const int* __restrict__ cnt,
                                 int* __restrict__ offs1, int* __restrict__ cur1,
                                 int* __restrict__ offs2, int* __restrict__ cur2) {
    const int n = (blockIdx.x == 0) ? N1c : N2c;
    const int* c = (blockIdx.x == 0) ? cnt : (cnt + N1c);
    int* offs = (blockIdx.x == 0) ? offs1 : offs2;
    int* cur  = (blockIdx.x == 0) ? cur1 : cur2;

    __shared__ int warpsums[32];
    __shared__ int s_carry;
    const int lane = threadIdx.x & 31;
    const int wid  = threadIdx.x >> 5;
    const int nw   = blockDim.x >> 5;
    if (threadIdx.x == 0) s_carry = 0;
    __syncthreads();
    for (int base = 0; base < n; base += blockDim.x) {
        int i = base + threadIdx.x;
        int v = (i < n) ? c[i] : 0;
        int carry = s_carry;
        int x = v;
        #pragma unroll
        for (int o = 1; o < 32; o <<= 1) {
            int y = __shfl_up_sync(0xFFFFFFFFu, x, o);
            if (lane >= o) x += y;
        }
        if (lane == 31) warpsums[wid] = x;
        __syncthreads();
        if (wid == 0) {
            int w = (lane < nw) ? warpsums[lane] : 0;
            #pragma unroll
            for (int o = 1; o < 32; o <<= 1) {
                int y = __shfl_up_sync(0xFFFFFFFFu, w, o);
                if (lane >= o) w += y;
            }
            warpsums[lane] = w;
        }
        __syncthreads();
        int incl = x + (wid > 0 ? warpsums[wid - 1] : 0) + carry;
        if (i < n) { offs[i] = incl - v; cur[i] = incl - v; }
        __syncthreads();
        if (threadIdx.x == blockDim.x - 1) s_carry = incl;
        __syncthreads();
    }
    if (threadIdx.x == 0) offs[n] = s_carry;
}

__global__ void fill_both_kernel(const int* __restrict__ src1, const int* __restrict__ dst1,
                                 const int* __restrict__ src2, const int* __restrict__ dst2,
                                 int* __restrict__ cur1, int* __restrict__ cur2,
                                 int* __restrict__ eid1, int* __restrict__ eid2) {
    int i = blockIdx.x * blockDim.x + threadIdx.x;
    if (i < E1c) {
        int pos = atomicAdd(&cur1[dst1[i]], 1);
        eid1[pos] = src1[i];
    } else if (i < E1c + E2c) {
        int j = i - E1c;
        int pos = atomicAdd(&cur2[dst2[j]], 1);
        eid2[pos] = src2[j];
    }
}

// ---------------- fused gather-mean + bf16 split helpers ---------------------------

__device__ __forceinline__ void split4_store(__nv_bfloat16* __restrict__ Ah,
                                             __nv_bfloat16* __restrict__ Al,
                                             size_t row, int col, float4 v) {
    __nv_bfloat16 h0 = __float2bfloat16(v.x);
    __nv_bfloat16 h1 = __float2bfloat16(v.y);
    __nv_bfloat16 h2 = __float2bfloat16(v.z);
    __nv_bfloat16 h3 = __float2bfloat16(v.w);
    __nv_bfloat16 l0 = __float2bfloat16(v.x - __bfloat162float(h0));
    __nv_bfloat16 l1 = __float2bfloat16(v.y - __bfloat162float(h1));
    __nv_bfloat16 l2 = __float2bfloat16(v.z - __bfloat162float(h2));
    __nv_bfloat16 l3 = __float2bfloat16(v.w - __bfloat162float(h3));
    uint2 uh, ul;
    uh.x = (uint32_t)__bfloat16_as_ushort(h0) | ((uint32_t)__bfloat16_as_ushort(h1) << 16);
    uh.y = (uint32_t)__bfloat16_as_ushort(h2) | ((uint32_t)__bfloat16_as_ushort(h3) << 16);
    ul.x = (uint32_t)__bfloat16_as_ushort(l0) | ((uint32_t)__bfloat16_as_ushort(l1) << 16);
    ul.y = (uint32_t)__bfloat16_as_ushort(l2) | ((uint32_t)__bfloat16_as_ushort(l3) << 16);
    *(uint2*)(Ah + row * 512 + col) = uh;
    *(uint2*)(Al + row * 512 + col) = ul;
}

// warp-level gather-mean + self + split for one dst row
__device__ __forceinline__ void gather_row(const float* __restrict__ X,
                                           const float* __restrict__ Self,
                                           const int* __restrict__ offs,
                                           const int* __restrict__ eid,
                                           __nv_bfloat16* __restrict__ Ah,
                                           __nv_bfloat16* __restrict__ Al,
                                           int w, int lane) {
    int beg = offs[w], end = offs[w + 1];
    float4 s0 = make_float4(0.f, 0.f, 0.f, 0.f);
    float4 s1 = s0;
    int e = beg;
    for (; e + 1 < end; e += 2) {
        int i0 = eid[e], i1 = eid[e + 1];
        const float4* r0 = (const float4*)(X + (size_t)i0 * Dc);
        const float4* r1 = (const float4*)(X + (size_t)i1 * Dc);
        float4 a0 = __ldg(&r0[lane]);
        float4 a1 = __ldg(&r0[lane + 32]);
        float4 b0 = __ldg(&r1[lane]);
        float4 b1 = __ldg(&r1[lane + 32]);
        s0.x += a0.x + b0.x; s0.y += a0.y + b0.y; s0.z += a0.z + b0.z; s0.w += a0.w + b0.w;
        s1.x += a1.x + b1.x; s1.y += a1.y + b1.y; s1.z += a1.z + b1.z; s1.w += a1.w + b1.w;
    }
    if (e < end) {
        int i0 = eid[e];
        const float4* r0 = (const float4*)(X + (size_t)i0 * Dc);
        float4 a0 = __ldg(&r0[lane]);
        float4 a1 = __ldg(&r0[lane + 32]);
        s0.x += a0.x; s0.y += a0.y; s0.z += a0.z; s0.w += a0.w;
        s1.x += a1.x; s1.y += a1.y; s1.z += a1.z; s1.w += a1.w;
    }
    float invd = 1.0f / (float)max(end - beg, 1);
    s0.x *= invd; s0.y *= invd; s0.z *= invd; s0.w *= invd;
    s1.x *= invd; s1.y *= invd; s1.z *= invd; s1.w *= invd;

    const float4* sr = (const float4*)(Self + (size_t)w * Dc);
    float4 t0 = __ldg(&sr[lane]);
    float4 t1 = __ldg(&sr[lane + 32]);

    split4_store(Ah, Al, (size_t)w, 4 * lane,       s0);
    split4_store(Ah, Al, (size_t)w, 128 + 4 * lane, s1);
    split4_store(Ah, Al, (size_t)w, 256 + 4 * lane, t0);
    split4_store(Ah, Al, (size_t)w, 384 + 4 * lane, t1);
}

__device__ __forceinline__ void convW_elem(const float* __restrict__ Wl,
                                           const float* __restrict__ Wr,
                                           __nv_bfloat16* __restrict__ Wh,
                                           __nv_bfloat16* __restrict__ Wlo,
                                           int NT, int idx) {
    int n = idx >> 9;
    int k = idx & 511;
    float v = (k < 256) ? Wl[(size_t)k * NT + n] : Wr[(size_t)(k - 256) * NT + n];
    __nv_bfloat16 hi = __float2bfloat16(v);
    __nv_bfloat16 lo = __float2bfloat16(v - __bfloat162float(hi));
    Wh[(size_t)n * 512 + k]  = hi;
    Wlo[(size_t)n * 512 + k] = lo;
}

// prep megakernel: gather1+convert | convertW1 | convertW2 in one grid
__global__ void prep_kernel(const float* __restrict__ x,
                            const int* __restrict__ offs1, const int* __restrict__ eid1,
                            __nv_bfloat16* __restrict__ A1h, __nv_bfloat16* __restrict__ A1l,
                            const float* __restrict__ W1l, const float* __restrict__ W1r,
                            __nv_bfloat16* __restrict__ W1h, __nv_bfloat16* __restrict__ W1lo,
                            const float* __restrict__ W2l, const float* __restrict__ W2r,
                            __nv_bfloat16* __restrict__ W2h, __nv_bfloat16* __restrict__ W2lo) {
    int b = blockIdx.x;
    if (b < GATHER1_BLOCKS) {
        int w    = b * 8 + (threadIdx.x >> 5);
        int lane = threadIdx.x & 31;
        if (w < N1c) gather_row(x, x, offs1, eid1, A1h, A1l, w, lane);
    } else if (b < GATHER1_BLOCKS + W1_BLOCKS) {
        int idx = (b - GATHER1_BLOCKS) * 256 + threadIdx.x;
        convW_elem(W1l, W1r, W1h, W1lo, Dc, idx);
    } else {
        int idx = (b - GATHER1_BLOCKS - W1_BLOCKS) * 256 + threadIdx.x;
        convW_elem(W2l, W2r, W2h, W2lo, DOUTc, idx);
    }
}

// layer-2 gather (after gemm1)
__global__ void gather2_kernel(const float* __restrict__ h,
                               const int* __restrict__ offs2, const int* __restrict__ eid2,
                               __nv_bfloat16* __restrict__ A2h, __nv_bfloat16* __restrict__ A2l) {
    int w    = (blockIdx.x * blockDim.x + threadIdx.x) >> 5;
    int lane = threadIdx.x & 31;
    if (w < N2c) gather_row(h, h, offs2, eid2, A2h, A2l, w, lane);
}

// ---------------- mma.sync bf16 3-split GEMM (unchanged) ---------------------------

#define SPAD 40
#define MAT_BYTES (128 * SPAD * 2)
#define STAGE_BYTES (4 * MAT_BYTES)
#define GEMM_SMEM (2 * STAGE_BYTES)

template <int NTOT, int ACT>
__global__ void __launch_bounds__(256, 1)
gemm_mma(const __nv_bfloat16* __restrict__ Ah, const __nv_bfloat16* __restrict__ Al,
         const __nv_bfloat16* __restrict__ Bh, const __nv_bfloat16* __restrict__ Bl,
         const float* __restrict__ bias, float* __restrict__ C, int M)
{
    extern __shared__ char smem[];
    const uint32_t sbase = smem_u32(smem);
    const int tid  = threadIdx.x;
    const int wid  = tid >> 5;
    const int lane = tid & 31;
    const int wm   = wid >> 2;
    const int wn   = wid & 3;
    const int g    = lane >> 2;
    const int t    = lane & 3;

    const int row0 = blockIdx.x * 128;
    const int col0 = blockIdx.y * 128;

    float acc[4][4][4];
    #pragma unroll
    for (int i = 0; i < 4; i++)
        #pragma unroll
        for (int j = 0; j < 4; j++)
            #pragma unroll
            for (int q = 0; q < 4; q++) acc[i][j][q] = 0.0f;

    auto load_stage = [&](int s, int k0) {
        uint32_t base = sbase + s * STAGE_BYTES;
        #pragma unroll
        for (int q8 = 0; q8 < 8; q8++) {
            int idx  = q8 * 256 + tid;
            int mat  = idx >> 9;
            int slot = idx & 511;
            int row  = slot >> 2;
            int quar = slot & 3;
            uint32_t dst = base + mat * MAT_BYTES + row * (SPAD * 2) + quar * 16;
            if (mat < 2) {
                int grow = row0 + row;
                int srow = grow < M ? grow : (M - 1);
                const __nv_bfloat16* src =
                    (mat == 0 ? Ah : Al) + (size_t)srow * 512 + k0 + quar * 8;
                cp16(dst, src, grow < M ? 16u : 0u);
            } else {
                const __nv_bfloat16* src =
                    (mat == 2 ? Bh : Bl) + (size_t)(col0 + row) * 512 + k0 + quar * 8;
                cp16(dst, src, 16u);
            }
        }
    };

    load_stage(0, 0);
    cp_commit();

    #pragma unroll 1
    for (int c = 0; c < 16; c++) {
        if (c < 15) {
            load_stage((c + 1) & 1, (c + 1) * 32);
            cp_commit();
            cp_wait<1>();
        } else {
            cp_wait<0>();
        }
        __syncthreads();

        const char* st  = smem + (c & 1) * STAGE_BYTES;
        const char* pAh = st;
        const char* pAl = st + MAT_BYTES;
        const char* pBh = st + 2 * MAT_BYTES;
        const char* pBl = st + 3 * MAT_BYTES;

        #pragma unroll
        for (int kk = 0; kk < 32; kk += 16) {
            uint32_t ah[4][4], al[4][4], bh[4][2], bl[4][2];
            #pragma unroll
            for (int i = 0; i < 4; i++) {
                int r = wm * 64 + i * 16 + g;
                int cb0 = (kk + 2 * t) * 2;
                const char* base0 = pAh + r * (SPAD * 2);
                const char* base1 = pAh + (r + 8) * (SPAD * 2);
                ah[i][0] = *(const uint32_t*)(base0 + cb0);
                ah[i][1] = *(const uint32_t*)(base1 + cb0);
                ah[i][2] = *(const uint32_t*)(base0 + cb0 + 16);
                ah[i][3] = *(const uint32_t*)(base1 + cb0 + 16);
                const char* base0l = pAl + r * (SPAD * 2);
                const char* base1l = pAl + (r + 8) * (SPAD * 2);
                al[i][0] = *(const uint32_t*)(base0l + cb0);
                al[i][1] = *(const uint32_t*)(base1l + cb0);
                al[i][2] = *(const uint32_t*)(base0l + cb0 + 16);
                al[i][3] = *(const uint32_t*)(base1l + cb0 + 16);
            }
            #pragma unroll
            for (int j = 0; j < 4; j++) {
                int n = wn * 32 + j * 8 + g;
                int cb0 = (kk + 2 * t) * 2;
                bh[j][0] = *(const uint32_t*)(pBh + n * (SPAD * 2) + cb0);
                bh[j][1] = *(const uint32_t*)(pBh + n * (SPAD * 2) + cb0 + 16);
                bl[j][0] = *(const uint32_t*)(pBl + n * (SPAD * 2) + cb0);
                bl[j][1] = *(const uint32_t*)(pBl + n * (SPAD * 2) + cb0 + 16);
            }
            #pragma unroll
            for (int i = 0; i < 4; i++)
                #pragma unroll
                for (int j = 0; j < 4; j++) {
                    mma16816(acc[i][j], ah[i], bh[j]);
                    mma16816(acc[i][j], ah[i], bl[j]);
                    mma16816(acc[i][j], al[i], bh[j]);
                }
        }
        __syncthreads();
    }

    #pragma unroll
    for (int j = 0; j < 4; j++) {
        int cidx = col0 + wn * 32 + j * 8 + 2 * t;
        float bx = bias[cidx], by = bias[cidx + 1];
        #pragma unroll
        for (int i = 0; i < 4; i++) {
            int r = row0 + wm * 64 + i * 16 + g;
            float v0 = acc[i][j][0] + bx;
            float v1 = acc[i][j][1] + by;
            float v2 = acc[i][j][2] + bx;
            float v3 = acc[i][j][3] + by;
            if (ACT == 0) {
                v0 = fmaxf(v0, 0.f); v1 = fmaxf(v1, 0.f);
                v2 = fmaxf(v2, 0.f); v3 = fmaxf(v3, 0.f);
            } else {
                v0 = 1.0f / (1.0f + expf(-v0));
                v1 = 1.0f / (1.0f + expf(-v1));
                v2 = 1.0f / (1.0f + expf(-v2));
                v3 = 1.0f / (1.0f + expf(-v3));
            }
            if (r < M)     *(float2*)(C + (size_t)r * NTOT + cidx)       = make_float2(v0, v1);
            if (r + 8 < M) *(float2*)(C + (size_t)(r + 8) * NTOT + cidx) = make_float2(v2, v3);
        }
    }
}

// ---------------- launch ----------------------------------------------------------

extern "C" void kernel_launch(void* const* d_in, const int* in_sizes, int n_in,
                              void* d_out, int out_size) {
    const float* x    = (const float*)d_in[0];
    const float* W1l  = (const float*)d_in[1];
    const float* b1   = (const float*)d_in[2];
    const float* W1r  = (const float*)d_in[3];
    const float* W2l  = (const float*)d_in[4];
    const float* b2   = (const float*)d_in[5];
    const float* W2r  = (const float*)d_in[6];
    const int*   src1 = (const int*)d_in[7];
    const int*   dst1 = (const int*)d_in[8];
    const int*   src2 = (const int*)d_in[9];
    const int*   dst2 = (const int*)d_in[10];
    float* out = (float*)d_out;

    void *p;
    float *h;
    int *cnt, *offs1, *offs2, *cur1, *cur2, *eid1, *eid2;
    __nv_bfloat16 *A1h, *A1l, *A2h, *A2l, *W1h_, *W1lo_, *W2h_, *W2lo_;
    cudaGetSymbolAddress(&p, g_h);     h     = (float*)p;
    cudaGetSymbolAddress(&p, g_cnt);   cnt   = (int*)p;
    cudaGetSymbolAddress(&p, g_offs1); offs1 = (int*)p;
    cudaGetSymbolAddress(&p, g_offs2); offs2 = (int*)p;
    cudaGetSymbolAddress(&p, g_cur1);  cur1  = (int*)p;
    cudaGetSymbolAddress(&p, g_cur2);  cur2  = (int*)p;
    cudaGetSymbolAddress(&p, g_eid1);  eid1  = (int*)p;
    cudaGetSymbolAddress(&p, g_eid2);  eid2  = (int*)p;
    cudaGetSymbolAddress(&p, g_A1h);   A1h   = (__nv_bfloat16*)p;
    cudaGetSymbolAddress(&p, g_A1l);   A1l   = (__nv_bfloat16*)p;
    cudaGetSymbolAddress(&p, g_A2h);   A2h   = (__nv_bfloat16*)p;
    cudaGetSymbolAddress(&p, g_A2l);   A2l   = (__nv_bfloat16*)p;
    cudaGetSymbolAddress(&p, g_W1h);   W1h_  = (__nv_bfloat16*)p;
    cudaGetSymbolAddress(&p, g_W1lo);  W1lo_ = (__nv_bfloat16*)p;
    cudaGetSymbolAddress(&p, g_W2h);   W2h_  = (__nv_bfloat16*)p;
    cudaGetSymbolAddress(&p, g_W2lo);  W2lo_ = (__nv_bfloat16*)p;

    cudaFuncSetAttribute(gemm_mma<256, 0>, cudaFuncAttributeMaxDynamicSharedMemorySize, GEMM_SMEM);
    cudaFuncSetAttribute(gemm_mma<128, 1>, cudaFuncAttributeMaxDynamicSharedMemorySize, GEMM_SMEM);

    // (0) one memset for both count arrays
    cudaMemsetAsync(cnt, 0, (size_t)(N1c + N2c) * sizeof(int), 0);

    // (1) count both layers
    count_both_kernel<<<(E1c + E2c + 255) / 256, 256>>>(dst1, dst2, cnt);
    // (2) scan both layers (2 blocks, parallel)
    scan_both_kernel<<<2, 1024>>>(cnt, offs1, cur1, offs2, cur2);
    // (3) fill both edge-id arrays
    fill_both_kernel<<<(E1c + E2c + 255) / 256, 256>>>(src1, dst1, src2, dst2,
                                                       cur1, cur2, eid1, eid2);
    // (4) prep: gather1+convert | convertW1 | convertW2
    prep_kernel<<<GATHER1_BLOCKS + W1_BLOCKS + W2_BLOCKS, 256>>>(
        x, offs1, eid1, A1h, A1l, W1l, W1r, W1h_, W1lo_, W2l, W2r, W2h_, W2lo_);
    // (5) gemm1  <-- ncu profiles this launch
    {
        dim3 grid((N1c + 127) / 128, 2);
        gemm_mma<256, 0><<<grid, 256, GEMM_SMEM>>>(A1h, A1l, W1h_, W1lo_, b1, h, N1c);
    }
    // (6) gather2
    gather2_kernel<<<(N2c * 32 + 255) / 256, 256>>>(h, offs2, eid2, A2h, A2l);
    // (7) gemm2
    {
        dim3 grid((N2c + 127) / 128, 1);
        gemm_mma<128, 1><<<grid, 256, GEMM_SMEM>>>(A2h, A2l, W2h_, W2lo_, b2, out, N2c);
    }
}